// round 2
// baseline (speedup 1.0000x reference)
#include <cuda_runtime.h>
#include <math.h>

#define B_ 4
#define S_ 2048
#define D_ 1024
#define H_ 16
#define DH_ 64
#define BS_ (B_ * S_)           // 8192
#define HD_ (H_ * DH_)          // 1024

// Scratch: Q,K,V projections + attention output (each 8192x1024 f32 = 33.5MB)
__device__ float g_Q[BS_ * HD_];
__device__ float g_K[BS_ * HD_];
__device__ float g_V[BS_ * HD_];
__device__ float g_AO[BS_ * HD_];

// ---------------------------------------------------------------------------
// Generic tiled SGEMM with bias: C[M,N] = A[M,K] @ B[K,N] + bias[N]
// 64x64 tile, BK=16, 256 threads, 4x4 per-thread micro-tile.
// M,N,K all divisible by 64/16 here (8192x1024x1024) -> no bounds checks.
// ---------------------------------------------------------------------------
__global__ void sgemm_bias_kernel(const float* __restrict__ A,
                                  const float* __restrict__ Bm,
                                  const float* __restrict__ bias,
                                  float* __restrict__ C,
                                  int M, int N, int K) {
    __shared__ float sA[16][65];   // [k][m]
    __shared__ float sB[16][65];   // [k][n]

    const int tx = threadIdx.x & 15;
    const int ty = threadIdx.x >> 4;
    const int m0 = blockIdx.y * 64;
    const int n0 = blockIdx.x * 64;

    float acc[4][4] = {};

    for (int k0 = 0; k0 < K; k0 += 16) {
        // load A tile 64x16 -> sA[k][m]
        #pragma unroll
        for (int i = threadIdx.x; i < 64 * 16; i += 256) {
            int m = i >> 4, kk = i & 15;
            sA[kk][m] = A[(size_t)(m0 + m) * K + k0 + kk];
        }
        // load B tile 16x64 -> sB[k][n]
        #pragma unroll
        for (int i = threadIdx.x; i < 16 * 64; i += 256) {
            int kk = i >> 6, n = i & 63;
            sB[kk][n] = Bm[(size_t)(k0 + kk) * N + n0 + n];
        }
        __syncthreads();

        #pragma unroll
        for (int kk = 0; kk < 16; kk++) {
            float a[4], b[4];
            #pragma unroll
            for (int i = 0; i < 4; i++) a[i] = sA[kk][ty * 4 + i];
            #pragma unroll
            for (int j = 0; j < 4; j++) b[j] = sB[kk][tx * 4 + j];
            #pragma unroll
            for (int i = 0; i < 4; i++)
                #pragma unroll
                for (int j = 0; j < 4; j++)
                    acc[i][j] = fmaf(a[i], b[j], acc[i][j]);
        }
        __syncthreads();
    }

    #pragma unroll
    for (int i = 0; i < 4; i++) {
        int m = m0 + ty * 4 + i;
        #pragma unroll
        for (int j = 0; j < 4; j++) {
            int n = n0 + tx * 4 + j;
            C[(size_t)m * N + n] = acc[i][j] + bias[n];
        }
    }
}

// ---------------------------------------------------------------------------
// Scores: alpha[b,h,q,k] = 0.125 * dot(Q[b,q,h,:], K[b,k,h,:])   (DH=64)
// Block computes 64x64 (q,k) tile; grid.z = b*H + h.
// ---------------------------------------------------------------------------
__global__ void scores_kernel(const float* __restrict__ Q,
                              const float* __restrict__ Kp,
                              float* __restrict__ alpha) {
    __shared__ float sQ[64][65];   // [d][q]
    __shared__ float sK[64][65];   // [d][k]

    const int bh = blockIdx.z;
    const int b = bh >> 4;           // / H_
    const int h = bh & 15;           // % H_
    const int q0 = blockIdx.y * 64;
    const int k0 = blockIdx.x * 64;

    // coalesced global read (row r, 64 consecutive d), transposed smem store
    #pragma unroll
    for (int i = threadIdx.x; i < 64 * 64; i += 256) {
        int r = i >> 6, d = i & 63;
        sQ[d][r] = Q[(size_t)(b * S_ + q0 + r) * HD_ + h * DH_ + d];
        sK[d][r] = Kp[(size_t)(b * S_ + k0 + r) * HD_ + h * DH_ + d];
    }
    __syncthreads();

    const int tx = threadIdx.x & 15;
    const int ty = threadIdx.x >> 4;
    float acc[4][4] = {};

    #pragma unroll 8
    for (int d = 0; d < 64; d++) {
        float qv[4], kv[4];
        #pragma unroll
        for (int i = 0; i < 4; i++) qv[i] = sQ[d][ty * 4 + i];
        #pragma unroll
        for (int j = 0; j < 4; j++) kv[j] = sK[d][tx * 4 + j];
        #pragma unroll
        for (int i = 0; i < 4; i++)
            #pragma unroll
            for (int j = 0; j < 4; j++)
                acc[i][j] = fmaf(qv[i], kv[j], acc[i][j]);
    }

    const float scale = 0.125f;  // 1/sqrt(64)
    #pragma unroll
    for (int i = 0; i < 4; i++) {
        size_t rowbase = ((size_t)bh * S_ + (q0 + ty * 4 + i)) * S_;
        #pragma unroll
        for (int j = 0; j < 4; j++)
            alpha[rowbase + k0 + tx * 4 + j] = acc[i][j] * scale;
    }
}

// ---------------------------------------------------------------------------
// Row softmax in place: one block (256 thr) per row of 2048. Values stay in
// registers (8/thread) -> single read + single write.
// ---------------------------------------------------------------------------
__global__ void softmax_kernel(float* __restrict__ alpha) {
    float* p = alpha + (size_t)blockIdx.x * S_;
    const int t = threadIdx.x;
    __shared__ float sred[8];

    float v[8];
    float m = -1e30f;
    #pragma unroll
    for (int j = 0; j < 8; j++) {
        v[j] = p[t + j * 256];
        m = fmaxf(m, v[j]);
    }
    #pragma unroll
    for (int o = 16; o > 0; o >>= 1) m = fmaxf(m, __shfl_xor_sync(0xffffffffu, m, o));
    if ((t & 31) == 0) sred[t >> 5] = m;
    __syncthreads();
    m = sred[0];
    #pragma unroll
    for (int w = 1; w < 8; w++) m = fmaxf(m, sred[w]);
    __syncthreads();

    float s = 0.f;
    #pragma unroll
    for (int j = 0; j < 8; j++) {
        v[j] = __expf(v[j] - m);
        s += v[j];
    }
    #pragma unroll
    for (int o = 16; o > 0; o >>= 1) s += __shfl_xor_sync(0xffffffffu, s, o);
    if ((t & 31) == 0) sred[t >> 5] = s;
    __syncthreads();
    s = sred[0];
    #pragma unroll
    for (int w = 1; w < 8; w++) s += sred[w];

    const float inv = 1.0f / s;
    #pragma unroll
    for (int j = 0; j < 8; j++) p[t + j * 256] = v[j] * inv;
}

// ---------------------------------------------------------------------------
// AV: AO[b,q,h,d] = sum_k alpha[b,h,q,k] * V[b,k,h,d]
// Block: 64 q-rows x 64 d (full DH); loop k in chunks of 64. grid = (S/64, B*H)
// ---------------------------------------------------------------------------
__global__ void av_kernel(const float* __restrict__ alpha,
                          const float* __restrict__ V,
                          float* __restrict__ AO) {
    __shared__ float sA[64][65];   // [q][k]
    __shared__ float sV[64][65];   // [k][d]

    const int bh = blockIdx.y;
    const int b = bh >> 4;
    const int h = bh & 15;
    const int q0 = blockIdx.x * 64;

    const int tx = threadIdx.x & 15;
    const int ty = threadIdx.x >> 4;
    float acc[4][4] = {};

    for (int k0 = 0; k0 < S_; k0 += 64) {
        #pragma unroll
        for (int i = threadIdx.x; i < 64 * 64; i += 256) {
            int r = i >> 6, c = i & 63;
            sA[r][c] = alpha[((size_t)bh * S_ + q0 + r) * S_ + k0 + c];
            sV[r][c] = V[(size_t)(b * S_ + k0 + r) * HD_ + h * DH_ + c];
        }
        __syncthreads();

        #pragma unroll 8
        for (int kk = 0; kk < 64; kk++) {
            float a[4], bv[4];
            #pragma unroll
            for (int i = 0; i < 4; i++) a[i] = sA[ty * 4 + i][kk];
            #pragma unroll
            for (int j = 0; j < 4; j++) bv[j] = sV[kk][tx * 4 + j];
            #pragma unroll
            for (int i = 0; i < 4; i++)
                #pragma unroll
                for (int j = 0; j < 4; j++)
                    acc[i][j] = fmaf(a[i], bv[j], acc[i][j]);
        }
        __syncthreads();
    }

    #pragma unroll
    for (int i = 0; i < 4; i++) {
        size_t row = (size_t)(b * S_ + q0 + ty * 4 + i) * HD_ + h * DH_;
        #pragma unroll
        for (int j = 0; j < 4; j++)
            AO[row + tx * 4 + j] = acc[i][j];
    }
}

// ---------------------------------------------------------------------------
extern "C" void kernel_launch(void* const* d_in, const int* in_sizes, int n_in,
                              void* d_out, int out_size) {
    const float* q  = (const float*)d_in[0];
    const float* k  = (const float*)d_in[1];
    const float* v  = (const float*)d_in[2];
    const float* Wq = (const float*)d_in[3];
    const float* bq = (const float*)d_in[4];
    const float* Wk = (const float*)d_in[5];
    const float* bk = (const float*)d_in[6];
    const float* Wv = (const float*)d_in[7];
    const float* bv = (const float*)d_in[8];
    const float* Wo = (const float*)d_in[9];
    const float* bo = (const float*)d_in[10];

    float* out   = (float*)d_out;
    float* alpha = out + (size_t)B_ * S_ * D_;   // out first, then alpha

    float *Qp, *Kp, *Vp, *AOp;
    cudaGetSymbolAddress((void**)&Qp,  g_Q);
    cudaGetSymbolAddress((void**)&Kp,  g_K);
    cudaGetSymbolAddress((void**)&Vp,  g_V);
    cudaGetSymbolAddress((void**)&AOp, g_AO);

    dim3 gProj(D_ / 64, BS_ / 64);     // (16, 128)
    sgemm_bias_kernel<<<gProj, 256>>>(q, Wq, bq, Qp, BS_, HD_, D_);
    sgemm_bias_kernel<<<gProj, 256>>>(k, Wk, bk, Kp, BS_, HD_, D_);
    sgemm_bias_kernel<<<gProj, 256>>>(v, Wv, bv, Vp, BS_, HD_, D_);

    dim3 gScores(S_ / 64, S_ / 64, B_ * H_);   // (32, 32, 64)
    scores_kernel<<<gScores, 256>>>(Qp, Kp, alpha);

    softmax_kernel<<<B_ * H_ * S_, 256>>>(alpha);   // 131072 rows

    dim3 gAV(S_ / 64, B_ * H_);        // (32, 64)
    av_kernel<<<gAV, 256>>>(alpha, Vp, AOp);

    sgemm_bias_kernel<<<gProj, 256>>>(AOp, Wo, bo, out, BS_, D_, HD_ /*K=1024*/ == 64 ? HD_ : HD_);
    // NOTE: K for out-proj is H*DH = 1024 = HD_; the expression above is HD_.
}

// round 3
// speedup vs baseline: 1.6067x; 1.6067x over previous
#include <cuda_runtime.h>
#include <cstdint>

#define B_ 4
#define S_ 2048
#define D_ 1024
#define H_ 16
#define DH_ 64
#define BS_ (B_ * S_)           // 8192
#define HD_ (H_ * DH_)          // 1024

// Scratch: Q,K,V projections + attention output (each 8192x1024 f32 = 33.5MB)
__device__ float g_Q[BS_ * HD_];
__device__ float g_K[BS_ * HD_];
__device__ float g_V[BS_ * HD_];
__device__ float g_AO[BS_ * HD_];

// ---------------------------------------------------------------------------
// tf32 helpers
// ---------------------------------------------------------------------------
__device__ __forceinline__ float tf32_rna(float x) {
    uint32_t u;
    asm("cvt.rna.tf32.f32 %0, %1;" : "=r"(u) : "f"(x));
    return __uint_as_float(u);
}

__device__ __forceinline__ void mma_tf32(float* d, const float* a, const float* b) {
    asm volatile(
        "mma.sync.aligned.m16n8k8.row.col.f32.tf32.tf32.f32 "
        "{%0,%1,%2,%3}, {%4,%5,%6,%7}, {%8,%9}, {%0,%1,%2,%3};"
        : "+f"(d[0]), "+f"(d[1]), "+f"(d[2]), "+f"(d[3])
        : "r"(__float_as_uint(a[0])), "r"(__float_as_uint(a[1])),
          "r"(__float_as_uint(a[2])), "r"(__float_as_uint(a[3])),
          "r"(__float_as_uint(b[0])), "r"(__float_as_uint(b[1])));
}

// ---------------------------------------------------------------------------
// Generic batched 3xTF32 tensor-core GEMM:
//   C[M,N] = scale * (A[M,K] @ B) (+ bias[N])
//   TRANSB=false: B is [K,N] row-major (n contiguous)
//   TRANSB=true : B is [N,K] row-major (k contiguous)  -> C = A @ B^T
// Batch index z = blockIdx.z is split z = b*16 + h; per-operand offset is
// b*So + h*Si (covers head-interleaved layouts with H=16).
// Block: 256 threads = 8 warps in 2(m) x 4(n); BK=16; mma m16n8k8.
// All problem dims here divide the tiles exactly -> no bounds checks.
// ---------------------------------------------------------------------------
template<int BM, int BN, bool TRANSB, bool HASBIAS>
__global__ void __launch_bounds__(256, 2)
gemm3tf32(const float* __restrict__ A, const float* __restrict__ Bm,
          const float* __restrict__ bias, float* __restrict__ C,
          int K, int lda, int ldb, int ldc,
          long long sAo, long long sAi, long long sBo, long long sBi,
          long long sCo, long long sCi, float scale) {
    constexpr int BK = 16;
    constexpr int PM = BM + 8;   // pitch -> conflict-free fragment loads
    constexpr int PN = BN + 8;
    __shared__ float sAh[BK][PM], sAl[BK][PM];
    __shared__ float sBh[BK][PN], sBl[BK][PN];

    const int tid = threadIdx.x;
    const int m0 = blockIdx.y * BM;
    const int n0 = blockIdx.x * BN;

    const int zb = blockIdx.z >> 4;
    const int zh = blockIdx.z & 15;
    const float* Ab = A + zb * sAo + zh * sAi;
    const float* Bb = Bm + zb * sBo + zh * sBi;
    float* Cb = C + zb * sCo + zh * sCi;

    const int w = tid >> 5;
    const int lane = tid & 31;
    const int g = lane >> 2, t = lane & 3;
    const int wr = w & 1, wc = w >> 1;          // 2 x 4 warp grid
    constexpr int WM = BM / 2, WN = BN / 4;
    constexpr int TM = WM / 16, TN = WN / 8;
    const int mw = wr * WM, nw = wc * WN;

    float acc[TM][TN][4];
    #pragma unroll
    for (int i = 0; i < TM; i++)
        #pragma unroll
        for (int j = 0; j < TN; j++)
            #pragma unroll
            for (int r = 0; r < 4; r++) acc[i][j][r] = 0.f;

    for (int k0 = 0; k0 < K; k0 += BK) {
        // ---- stage A: BM x 16, k contiguous in global ----
        {
            int mm = tid >> 2;
            const int kq = (tid & 3) * 4;
            #pragma unroll
            for (int r = 0; r < BM / 64; r++, mm += 64) {
                float4 v = *(const float4*)(Ab + (long long)(m0 + mm) * lda + k0 + kq);
                float hh;
                hh = tf32_rna(v.x); sAh[kq + 0][mm] = hh; sAl[kq + 0][mm] = v.x - hh;
                hh = tf32_rna(v.y); sAh[kq + 1][mm] = hh; sAl[kq + 1][mm] = v.y - hh;
                hh = tf32_rna(v.z); sAh[kq + 2][mm] = hh; sAl[kq + 2][mm] = v.z - hh;
                hh = tf32_rna(v.w); sAh[kq + 3][mm] = hh; sAl[kq + 3][mm] = v.w - hh;
            }
        }
        // ---- stage B ----
        if (TRANSB) {
            // B is [N][K], k contiguous: same shape as A staging
            int nn = tid >> 2;
            const int kq = (tid & 3) * 4;
            #pragma unroll
            for (int r = 0; r < BN / 64; r++, nn += 64) {
                float4 v = *(const float4*)(Bb + (long long)(n0 + nn) * ldb + k0 + kq);
                float hh;
                hh = tf32_rna(v.x); sBh[kq + 0][nn] = hh; sBl[kq + 0][nn] = v.x - hh;
                hh = tf32_rna(v.y); sBh[kq + 1][nn] = hh; sBl[kq + 1][nn] = v.y - hh;
                hh = tf32_rna(v.z); sBh[kq + 2][nn] = hh; sBl[kq + 2][nn] = v.z - hh;
                hh = tf32_rna(v.w); sBh[kq + 3][nn] = hh; sBl[kq + 3][nn] = v.w - hh;
            }
        } else {
            // B is [K][N], n contiguous: vector along n
            #pragma unroll
            for (int idx = tid; idx < BK * BN / 4; idx += 256) {
                const int kk = idx / (BN / 4);
                const int nq = (idx % (BN / 4)) * 4;
                float4 v = *(const float4*)(Bb + (long long)(k0 + kk) * ldb + n0 + nq);
                float4 hv, lv;
                hv.x = tf32_rna(v.x); lv.x = v.x - hv.x;
                hv.y = tf32_rna(v.y); lv.y = v.y - hv.y;
                hv.z = tf32_rna(v.z); lv.z = v.z - hv.z;
                hv.w = tf32_rna(v.w); lv.w = v.w - hv.w;
                *(float4*)&sBh[kk][nq] = hv;
                *(float4*)&sBl[kk][nq] = lv;
            }
        }
        __syncthreads();

        // ---- compute: two k8 micro-steps ----
        #pragma unroll
        for (int kk = 0; kk < BK; kk += 8) {
            float bh[TN][2], bl[TN][2];
            #pragma unroll
            for (int j = 0; j < TN; j++) {
                const int n = nw + j * 8 + g;
                bh[j][0] = sBh[kk + t][n];     bh[j][1] = sBh[kk + t + 4][n];
                bl[j][0] = sBl[kk + t][n];     bl[j][1] = sBl[kk + t + 4][n];
            }
            #pragma unroll
            for (int i = 0; i < TM; i++) {
                const int m = mw + i * 16 + g;
                float ah[4], al[4];
                ah[0] = sAh[kk + t][m];       ah[1] = sAh[kk + t][m + 8];
                ah[2] = sAh[kk + t + 4][m];   ah[3] = sAh[kk + t + 4][m + 8];
                al[0] = sAl[kk + t][m];       al[1] = sAl[kk + t][m + 8];
                al[2] = sAl[kk + t + 4][m];   al[3] = sAl[kk + t + 4][m + 8];
                #pragma unroll
                for (int j = 0; j < TN; j++) {
                    mma_tf32(acc[i][j], ah, bh[j]);   // hi*hi
                    mma_tf32(acc[i][j], al, bh[j]);   // lo*hi
                    mma_tf32(acc[i][j], ah, bl[j]);   // hi*lo
                }
            }
        }
        __syncthreads();
    }

    // ---- epilogue ----
    #pragma unroll
    for (int i = 0; i < TM; i++) {
        #pragma unroll
        for (int j = 0; j < TN; j++) {
            const int row = m0 + mw + i * 16 + g;
            const int col = n0 + nw + j * 8 + t * 2;
            float b0 = 0.f, b1 = 0.f;
            if (HASBIAS) { b0 = bias[col]; b1 = bias[col + 1]; }
            Cb[(long long)row * ldc + col]           = acc[i][j][0] * scale + b0;
            Cb[(long long)row * ldc + col + 1]       = acc[i][j][1] * scale + b1;
            Cb[(long long)(row + 8) * ldc + col]     = acc[i][j][2] * scale + b0;
            Cb[(long long)(row + 8) * ldc + col + 1] = acc[i][j][3] * scale + b1;
        }
    }
}

// ---------------------------------------------------------------------------
// Row softmax in place: one block (256 thr) per row of 2048.
// ---------------------------------------------------------------------------
__global__ void softmax_kernel(float* __restrict__ alpha) {
    float* p = alpha + (size_t)blockIdx.x * S_;
    const int t = threadIdx.x;
    __shared__ float sred[8];

    float v[8];
    float m = -1e30f;
    #pragma unroll
    for (int j = 0; j < 8; j++) {
        v[j] = p[t + j * 256];
        m = fmaxf(m, v[j]);
    }
    #pragma unroll
    for (int o = 16; o > 0; o >>= 1) m = fmaxf(m, __shfl_xor_sync(0xffffffffu, m, o));
    if ((t & 31) == 0) sred[t >> 5] = m;
    __syncthreads();
    m = sred[0];
    #pragma unroll
    for (int w = 1; w < 8; w++) m = fmaxf(m, sred[w]);
    __syncthreads();

    float s = 0.f;
    #pragma unroll
    for (int j = 0; j < 8; j++) {
        v[j] = __expf(v[j] - m);
        s += v[j];
    }
    #pragma unroll
    for (int o = 16; o > 0; o >>= 1) s += __shfl_xor_sync(0xffffffffu, s, o);
    if ((t & 31) == 0) sred[t >> 5] = s;
    __syncthreads();
    s = sred[0];
    #pragma unroll
    for (int w = 1; w < 8; w++) s += sred[w];

    const float inv = 1.0f / s;
    #pragma unroll
    for (int j = 0; j < 8; j++) p[t + j * 256] = v[j] * inv;
}

// ---------------------------------------------------------------------------
extern "C" void kernel_launch(void* const* d_in, const int* in_sizes, int n_in,
                              void* d_out, int out_size) {
    const float* q  = (const float*)d_in[0];
    const float* k  = (const float*)d_in[1];
    const float* v  = (const float*)d_in[2];
    const float* Wq = (const float*)d_in[3];
    const float* bq = (const float*)d_in[4];
    const float* Wk = (const float*)d_in[5];
    const float* bk = (const float*)d_in[6];
    const float* Wv = (const float*)d_in[7];
    const float* bv = (const float*)d_in[8];
    const float* Wo = (const float*)d_in[9];
    const float* bo = (const float*)d_in[10];

    float* out   = (float*)d_out;
    float* alpha = out + (size_t)B_ * S_ * D_;   // out first, then alpha

    float *Qp, *Kp, *Vp, *AOp;
    cudaGetSymbolAddress((void**)&Qp,  g_Q);
    cudaGetSymbolAddress((void**)&Kp,  g_K);
    cudaGetSymbolAddress((void**)&Vp,  g_V);
    cudaGetSymbolAddress((void**)&AOp, g_AO);

    const long long SS   = (long long)S_ * S_;
    const long long SHD  = (long long)S_ * HD_;

    // ---- QKV projections: [8192,1024] = [8192,1024] @ [1024,1024] + bias ----
    dim3 gProj(HD_ / 128, BS_ / 128);            // (8, 64)
    gemm3tf32<128, 128, false, true><<<gProj, 256>>>(
        q, Wq, bq, Qp, D_, D_, HD_, HD_, 0, 0, 0, 0, 0, 0, 1.f);
    gemm3tf32<128, 128, false, true><<<gProj, 256>>>(
        k, Wk, bk, Kp, D_, D_, HD_, HD_, 0, 0, 0, 0, 0, 0, 1.f);
    gemm3tf32<128, 128, false, true><<<gProj, 256>>>(
        v, Wv, bv, Vp, D_, D_, HD_, HD_, 0, 0, 0, 0, 0, 0, 1.f);

    // ---- scores: alpha[bh] = 0.125 * Q_bh[2048,64] @ K_bh[2048,64]^T ----
    dim3 gScores(S_ / 128, S_ / 128, B_ * H_);   // (16, 16, 64)
    gemm3tf32<128, 128, true, false><<<gScores, 256>>>(
        Qp, Kp, nullptr, alpha, DH_, HD_, HD_, S_,
        SHD, DH_,            // A offsets: b*S*HD + h*DH
        SHD, DH_,            // B offsets: same
        16LL * SS, SS,       // C offsets: (b*16 + h) * S*S
        0.125f);

    // ---- softmax in place on alpha ----
    softmax_kernel<<<B_ * H_ * S_, 256>>>(alpha);   // 131072 rows

    // ---- AV: AO_bh[2048,64] = alpha_bh[2048,2048] @ V_bh[2048,64] ----
    dim3 gAV(1, S_ / 128, B_ * H_);              // (1, 16, 64)
    gemm3tf32<128, 64, false, false><<<gAV, 256>>>(
        alpha, Vp, nullptr, AOp, S_, S_, HD_, HD_,
        16LL * SS, SS,       // A: alpha batch
        SHD, DH_,            // B: V head slice
        SHD, DH_,            // C: AO head slice
        1.f);

    // ---- output projection: out = AO @ Wo + bo ----
    gemm3tf32<128, 128, false, true><<<gProj, 256>>>(
        AOp, Wo, bo, out, HD_, HD_, D_, D_, 0, 0, 0, 0, 0, 0, 1.f);
}

// round 4
// speedup vs baseline: 1.9267x; 1.1992x over previous
#include <cuda_runtime.h>
#include <cstdint>

#define B_ 4
#define S_ 2048
#define D_ 1024
#define H_ 16
#define DH_ 64
#define BS_ (B_ * S_)           // 8192
#define HD_ (H_ * DH_)          // 1024

// Scratch
__device__ float g_Q[BS_ * HD_];
__device__ float g_K[BS_ * HD_];
__device__ float g_V[BS_ * HD_];
__device__ float g_AO[BS_ * HD_];

// ---------------------------------------------------------------------------
__device__ __forceinline__ float tf32_rna(float x) {
    uint32_t u;
    asm("cvt.rna.tf32.f32 %0, %1;" : "=r"(u) : "f"(x));
    return __uint_as_float(u);
}

__device__ __forceinline__ void mma_tf32(float* d, const float* a, const float* b) {
    asm volatile(
        "mma.sync.aligned.m16n8k8.row.col.f32.tf32.tf32.f32 "
        "{%0,%1,%2,%3}, {%4,%5,%6,%7}, {%8,%9}, {%0,%1,%2,%3};"
        : "+f"(d[0]), "+f"(d[1]), "+f"(d[2]), "+f"(d[3])
        : "r"(__float_as_uint(a[0])), "r"(__float_as_uint(a[1])),
          "r"(__float_as_uint(a[2])), "r"(__float_as_uint(a[3])),
          "r"(__float_as_uint(b[0])), "r"(__float_as_uint(b[1])));
}

__device__ __forceinline__ void cp16(uint32_t s, const void* g) {
    asm volatile("cp.async.cg.shared.global [%0], [%1], 16;" :: "r"(s), "l"(g));
}
#define CP_COMMIT asm volatile("cp.async.commit_group;")
#define CP_WAIT0  asm volatile("cp.async.wait_group 0;" ::: "memory")
#define CP_WAIT1  asm volatile("cp.async.wait_group 1;" ::: "memory")

// split helper: v -> hi (tf32) + lo
__device__ __forceinline__ void split2(float v, float& hi, float& lo) {
    hi = tf32_rna(v); lo = v - hi;
}

// ---------------------------------------------------------------------------
// Projection GEMM: C[8192,1024] = A[8192,1024] @ B[1024,1024] + bias
// raw-fp32 smem, on-the-fly tf32 split, cp.async double-buffered, BK=16.
// ---------------------------------------------------------------------------
#define PA 20    // A smem pitch (16 + 4)
#define PB 136   // B smem pitch (128 + 8)

__global__ void __launch_bounds__(256, 2)
proj_gemm(const float* __restrict__ A, const float* __restrict__ Bm,
          const float* __restrict__ bias, float* __restrict__ C) {
    __shared__ float sA[2][128 * PA];
    __shared__ float sB[2][16 * PB];

    const int tid = threadIdx.x;
    const int m0 = blockIdx.y * 128, n0 = blockIdx.x * 128;
    const int w = tid >> 5, lane = tid & 31, g = lane >> 2, t = lane & 3;
    const int mw = (w & 1) * 64, nw = (w >> 1) * 32;

    const uint32_t sAu = (uint32_t)__cvta_generic_to_shared(&sA[0][0]);
    const uint32_t sBu = (uint32_t)__cvta_generic_to_shared(&sB[0][0]);

    float acc[4][4][4] = {};

    // stage tile `it` into buffer `buf`
    auto stage = [&](int it, int buf) {
        const int k0 = it * 16;
        #pragma unroll
        for (int r = 0; r < 2; r++) {
            int c = tid + r * 256;
            int m = c >> 2, kq = (c & 3) * 4;
            cp16(sAu + (uint32_t)(buf * 128 * PA + m * PA + kq) * 4,
                 A + (size_t)(m0 + m) * 1024 + k0 + kq);
        }
        #pragma unroll
        for (int r = 0; r < 2; r++) {
            int c = tid + r * 256;
            int kk = c >> 5, nq = (c & 31) * 4;
            cp16(sBu + (uint32_t)(buf * 16 * PB + kk * PB + nq) * 4,
                 Bm + (size_t)(k0 + kk) * 1024 + n0 + nq);
        }
    };

    stage(0, 0); CP_COMMIT;

    for (int it = 0; it < 64; it++) {
        const int buf = it & 1;
        if (it + 1 < 64) { stage(it + 1, buf ^ 1); CP_COMMIT; CP_WAIT1; }
        else             { CP_WAIT0; }
        __syncthreads();

        const float* pA = &sA[buf][0];
        const float* pB = &sB[buf][0];

        #pragma unroll
        for (int kk = 0; kk < 16; kk += 8) {
            float bh[4][2], bl[4][2];
            #pragma unroll
            for (int j = 0; j < 4; j++) {
                const int n = nw + j * 8 + g;
                split2(pB[(kk + t) * PB + n],     bh[j][0], bl[j][0]);
                split2(pB[(kk + t + 4) * PB + n], bh[j][1], bl[j][1]);
            }
            #pragma unroll
            for (int i = 0; i < 4; i++) {
                const int m = mw + i * 16 + g;
                float ah[4], al[4];
                split2(pA[m * PA + kk + t],           ah[0], al[0]);
                split2(pA[(m + 8) * PA + kk + t],     ah[1], al[1]);
                split2(pA[m * PA + kk + t + 4],       ah[2], al[2]);
                split2(pA[(m + 8) * PA + kk + t + 4], ah[3], al[3]);
                #pragma unroll
                for (int j = 0; j < 4; j++) {
                    mma_tf32(acc[i][j], ah, bh[j]);
                    mma_tf32(acc[i][j], al, bh[j]);
                    mma_tf32(acc[i][j], ah, bl[j]);
                }
            }
        }
        __syncthreads();
    }

    #pragma unroll
    for (int i = 0; i < 4; i++) {
        #pragma unroll
        for (int j = 0; j < 4; j++) {
            const int row = m0 + mw + i * 16 + g;
            const int col = n0 + nw + j * 8 + t * 2;
            const float2 bv = *(const float2*)&bias[col];
            float2 o0 = { acc[i][j][0] + bv.x, acc[i][j][1] + bv.y };
            float2 o1 = { acc[i][j][2] + bv.x, acc[i][j][3] + bv.y };
            *(float2*)&C[(size_t)row * 1024 + col]       = o0;
            *(float2*)&C[(size_t)(row + 8) * 1024 + col] = o1;
        }
    }
}

// ---------------------------------------------------------------------------
// Fused attention: per CTA = one (q-tile of 128, bh).
// Pass A: S = 0.125*Q*K^T over 16 k-tiles, write raw S to alpha, online m/l.
// Pass B: re-read raw S, P = exp(S-m)/l -> alpha, O += P*V (3xTF32 MMA).
// Dynamic smem layout (floats):
//   [0]        sQ   128*68   (pass B: sV 64*72 overlays here)
//   [8704]     sK0  128*68   (pass B: sP here)
//   [17408]    sK1  128*68
//   [26112]    sM   128
//   [26240]    sF   128   (exp(m_old - m_new))
//   [26368]    sL   128   (l, then 1/l)
//   [26496]    sRed 512
// total 27008 floats = 108032 B
// ---------------------------------------------------------------------------
#define PQ 68
#define PV 72
#define ATTN_SMEM_FLOATS 27008

__global__ void __launch_bounds__(256, 2)
attn_fused(const float* __restrict__ Q, const float* __restrict__ Kp,
           const float* __restrict__ V, float* __restrict__ alpha,
           float* __restrict__ AO) {
    extern __shared__ float sm[];
    float* sQ   = sm;
    float* sK0  = sm + 8704;
    float* sK1  = sm + 17408;
    float* sM   = sm + 26112;
    float* sF   = sm + 26240;
    float* sL   = sm + 26368;
    float* sRed = sm + 26496;

    const int tid = threadIdx.x;
    const int w = tid >> 5, lane = tid & 31, g = lane >> 2, t = lane & 3;
    const int mw = (w & 1) * 64;
    const int wc = w >> 1;                 // 0..3
    const int q0 = blockIdx.x * 128;
    const int bh = blockIdx.y;
    const int b = bh >> 4, h = bh & 15;

    const float* Qb = Q + ((size_t)b * S_ + q0) * HD_ + h * DH_;
    const float* Kb = Kp + (size_t)b * S_ * HD_ + h * DH_;
    const float* Vb = V  + (size_t)b * S_ * HD_ + h * DH_;
    float* Ab = alpha + ((size_t)bh * S_ + q0) * S_;

    const uint32_t sQu  = (uint32_t)__cvta_generic_to_shared(sQ);
    const uint32_t sK0u = (uint32_t)__cvta_generic_to_shared(sK0);
    const uint32_t sK1u = (uint32_t)__cvta_generic_to_shared(sK1);

    if (tid < 128) { sM[tid] = -3e38f; sL[tid] = 0.f; }

    // ---- stage Q (once) + K tile 0 ----
    #pragma unroll
    for (int r = 0; r < 8; r++) {
        int c = tid + r * 256;
        int row = c >> 4, cq = (c & 15) * 4;
        cp16(sQu + (uint32_t)(row * PQ + cq) * 4, Qb + (size_t)row * HD_ + cq);
    }
    auto stageK = [&](int kt, uint32_t dstu) {
        const float* src = Kb + (size_t)kt * 128 * HD_;
        #pragma unroll
        for (int r = 0; r < 8; r++) {
            int c = tid + r * 256;
            int row = c >> 4, cq = (c & 15) * 4;
            cp16(dstu + (uint32_t)(row * PQ + cq) * 4, src + (size_t)row * HD_ + cq);
        }
    };
    stageK(0, sK0u);
    CP_COMMIT;

    // =================== PASS A ===================
    for (int kt = 0; kt < 16; kt++) {
        const float* pK = (kt & 1) ? sK1 : sK0;
        if (kt + 1 < 16) { stageK(kt + 1, (kt & 1) ? sK0u : sK1u); CP_COMMIT; CP_WAIT1; }
        else             { CP_WAIT0; }
        __syncthreads();

        float acc[4][4][4] = {};
        #pragma unroll
        for (int kk = 0; kk < 64; kk += 8) {
            float bh2[4][2], bl2[4][2];
            #pragma unroll
            for (int j = 0; j < 4; j++) {
                const int n = wc * 32 + j * 8 + g;
                split2(pK[n * PQ + kk + t],     bh2[j][0], bl2[j][0]);
                split2(pK[n * PQ + kk + t + 4], bh2[j][1], bl2[j][1]);
            }
            #pragma unroll
            for (int i = 0; i < 4; i++) {
                const int m = mw + i * 16 + g;
                float ah[4], al[4];
                split2(sQ[m * PQ + kk + t],           ah[0], al[0]);
                split2(sQ[(m + 8) * PQ + kk + t],     ah[1], al[1]);
                split2(sQ[m * PQ + kk + t + 4],       ah[2], al[2]);
                split2(sQ[(m + 8) * PQ + kk + t + 4], ah[3], al[3]);
                #pragma unroll
                for (int j = 0; j < 4; j++) {
                    mma_tf32(acc[i][j], ah, bh2[j]);
                    mma_tf32(acc[i][j], al, bh2[j]);
                    mma_tf32(acc[i][j], ah, bl2[j]);
                }
            }
        }
        // scale + write raw S
        #pragma unroll
        for (int i = 0; i < 4; i++)
            #pragma unroll
            for (int j = 0; j < 4; j++)
                #pragma unroll
                for (int r = 0; r < 4; r++) acc[i][j][r] *= 0.125f;

        #pragma unroll
        for (int i = 0; i < 4; i++) {
            const int row = mw + i * 16 + g;
            const int col = kt * 128 + wc * 32 + g * 0; // base; per-j below
            #pragma unroll
            for (int j = 0; j < 4; j++) {
                const int cc = kt * 128 + wc * 32 + j * 8 + t * 2;
                *(float2*)&Ab[(size_t)row * S_ + cc]       = make_float2(acc[i][j][0], acc[i][j][1]);
                *(float2*)&Ab[(size_t)(row + 8) * S_ + cc] = make_float2(acc[i][j][2], acc[i][j][3]);
            }
            (void)col;
        }

        // ---- row max ----
        float rmax[8];
        #pragma unroll
        for (int i = 0; i < 4; i++) {
            float m0v = -3e38f, m1v = -3e38f;
            #pragma unroll
            for (int j = 0; j < 4; j++) {
                m0v = fmaxf(m0v, fmaxf(acc[i][j][0], acc[i][j][1]));
                m1v = fmaxf(m1v, fmaxf(acc[i][j][2], acc[i][j][3]));
            }
            rmax[i * 2] = m0v; rmax[i * 2 + 1] = m1v;
        }
        #pragma unroll
        for (int o = 1; o <= 2; o <<= 1)
            #pragma unroll
            for (int e = 0; e < 8; e++)
                rmax[e] = fmaxf(rmax[e], __shfl_xor_sync(0xffffffffu, rmax[e], o));
        if (t == 0) {
            #pragma unroll
            for (int i = 0; i < 4; i++) {
                sRed[wc * 128 + mw + i * 16 + g]     = rmax[i * 2];
                sRed[wc * 128 + mw + i * 16 + g + 8] = rmax[i * 2 + 1];
            }
        }
        __syncthreads();
        if (tid < 128) {
            float tm = fmaxf(fmaxf(sRed[tid], sRed[128 + tid]),
                             fmaxf(sRed[256 + tid], sRed[384 + tid]));
            float mo = sM[tid];
            float mn = fmaxf(mo, tm);
            sM[tid] = mn;
            sF[tid] = __expf(mo - mn);
        }
        __syncthreads();

        // ---- row sum of exp ----
        float rsum[8];
        #pragma unroll
        for (int i = 0; i < 4; i++) {
            const int row = mw + i * 16 + g;
            const float mn0 = sM[row], mn1 = sM[row + 8];
            float s0 = 0.f, s1 = 0.f;
            #pragma unroll
            for (int j = 0; j < 4; j++) {
                s0 += __expf(acc[i][j][0] - mn0) + __expf(acc[i][j][1] - mn0);
                s1 += __expf(acc[i][j][2] - mn1) + __expf(acc[i][j][3] - mn1);
            }
            rsum[i * 2] = s0; rsum[i * 2 + 1] = s1;
        }
        #pragma unroll
        for (int o = 1; o <= 2; o <<= 1)
            #pragma unroll
            for (int e = 0; e < 8; e++)
                rsum[e] += __shfl_xor_sync(0xffffffffu, rsum[e], o);
        if (t == 0) {
            #pragma unroll
            for (int i = 0; i < 4; i++) {
                sRed[wc * 128 + mw + i * 16 + g]     = rsum[i * 2];
                sRed[wc * 128 + mw + i * 16 + g + 8] = rsum[i * 2 + 1];
            }
        }
        __syncthreads();
        if (tid < 128) {
            sL[tid] = sL[tid] * sF[tid] +
                      (sRed[tid] + sRed[128 + tid] + sRed[256 + tid] + sRed[384 + tid]);
        }
        __syncthreads();
    }

    // invert l
    if (tid < 128) sL[tid] = 1.0f / sL[tid];
    __syncthreads();

    // =================== PASS B ===================
    float* sP = sK0;        // 128 x PQ
    float* sV = sQ;         // 64 x PV (Q is dead)
    const uint32_t sVu = sQu;

    float accO[4][2][4] = {};
    const int pr = tid & 127;             // P row handled by this thread
    const int pc = (tid >> 7) * 32;       // col half
    const float rm = sM[pr];
    const float rl = sL[pr];

    for (int ch = 0; ch < 32; ch++) {
        const int kb = ch * 64;
        // stage V chunk (64 x 64) via cp.async
        {
            const float* src = Vb + (size_t)kb * HD_;
            #pragma unroll
            for (int r = 0; r < 4; r++) {
                int c = tid + r * 256;
                int vk = c >> 4, cq = (c & 15) * 4;
                cp16(sVu + (uint32_t)(vk * PV + cq) * 4, src + (size_t)vk * HD_ + cq);
            }
            CP_COMMIT;
        }
        // P: read raw S, exp-normalize, write alpha + smem
        {
            float* rowp = Ab + (size_t)pr * S_ + kb + pc;
            float* sprow = sP + pr * PQ + pc;
            #pragma unroll
            for (int u = 0; u < 8; u++) {
                float4 s4 = *(const float4*)(rowp + u * 4);
                float4 p4;
                p4.x = __expf(s4.x - rm) * rl;
                p4.y = __expf(s4.y - rm) * rl;
                p4.z = __expf(s4.z - rm) * rl;
                p4.w = __expf(s4.w - rm) * rl;
                *(float4*)(rowp + u * 4) = p4;
                *(float4*)(sprow + u * 4) = p4;
            }
        }
        CP_WAIT0;
        __syncthreads();

        // O += P * V  (3xTF32)
        #pragma unroll
        for (int kk = 0; kk < 64; kk += 8) {
            float bh2[2][2], bl2[2][2];
            #pragma unroll
            for (int j = 0; j < 2; j++) {
                const int n = wc * 16 + j * 8 + g;
                split2(sV[(kk + t) * PV + n],     bh2[j][0], bl2[j][0]);
                split2(sV[(kk + t + 4) * PV + n], bh2[j][1], bl2[j][1]);
            }
            #pragma unroll
            for (int i = 0; i < 4; i++) {
                const int m = mw + i * 16 + g;
                float ah[4], al[4];
                split2(sP[m * PQ + kk + t],           ah[0], al[0]);
                split2(sP[(m + 8) * PQ + kk + t],     ah[1], al[1]);
                split2(sP[m * PQ + kk + t + 4],       ah[2], al[2]);
                split2(sP[(m + 8) * PQ + kk + t + 4], ah[3], al[3]);
                #pragma unroll
                for (int j = 0; j < 2; j++) {
                    mma_tf32(accO[i][j], ah, bh2[j]);
                    mma_tf32(accO[i][j], al, bh2[j]);
                    mma_tf32(accO[i][j], ah, bl2[j]);
                }
            }
        }
        __syncthreads();
    }

    // epilogue: write AO
    #pragma unroll
    for (int i = 0; i < 4; i++) {
        #pragma unroll
        for (int j = 0; j < 2; j++) {
            const int row = q0 + mw + i * 16 + g;
            const int col = wc * 16 + j * 8 + t * 2;
            *(float2*)&AO[((size_t)(b * S_ + row)) * HD_ + h * DH_ + col] =
                make_float2(accO[i][j][0], accO[i][j][1]);
            *(float2*)&AO[((size_t)(b * S_ + row + 8)) * HD_ + h * DH_ + col] =
                make_float2(accO[i][j][2], accO[i][j][3]);
        }
    }
}

// ---------------------------------------------------------------------------
extern "C" void kernel_launch(void* const* d_in, const int* in_sizes, int n_in,
                              void* d_out, int out_size) {
    const float* q  = (const float*)d_in[0];
    const float* k  = (const float*)d_in[1];
    const float* v  = (const float*)d_in[2];
    const float* Wq = (const float*)d_in[3];
    const float* bq = (const float*)d_in[4];
    const float* Wk = (const float*)d_in[5];
    const float* bk = (const float*)d_in[6];
    const float* Wv = (const float*)d_in[7];
    const float* bv = (const float*)d_in[8];
    const float* Wo = (const float*)d_in[9];
    const float* bo = (const float*)d_in[10];

    float* out   = (float*)d_out;
    float* alpha = out + (size_t)B_ * S_ * D_;

    float *Qp, *Kp, *Vp, *AOp;
    cudaGetSymbolAddress((void**)&Qp,  g_Q);
    cudaGetSymbolAddress((void**)&Kp,  g_K);
    cudaGetSymbolAddress((void**)&Vp,  g_V);
    cudaGetSymbolAddress((void**)&AOp, g_AO);

    static bool attr_set = false;
    if (!attr_set) {
        cudaFuncSetAttribute(attn_fused, cudaFuncAttributeMaxDynamicSharedMemorySize,
                             ATTN_SMEM_FLOATS * 4);
        attr_set = true;
    }

    dim3 gProj(HD_ / 128, BS_ / 128);            // (8, 64)
    proj_gemm<<<gProj, 256>>>(q, Wq, bq, Qp);
    proj_gemm<<<gProj, 256>>>(k, Wk, bk, Kp);
    proj_gemm<<<gProj, 256>>>(v, Wv, bv, Vp);

    dim3 gAttn(S_ / 128, B_ * H_);               // (16, 64)
    attn_fused<<<gAttn, 256, ATTN_SMEM_FLOATS * 4>>>(Qp, Kp, Vp, alpha, AOp);

    proj_gemm<<<gProj, 256>>>(AOp, Wo, bo, out);
}

// round 5
// speedup vs baseline: 2.5507x; 1.3239x over previous
#include <cuda_runtime.h>
#include <cuda_bf16.h>
#include <cstdint>

#define B_ 4
#define S_ 2048
#define D_ 1024
#define H_ 16
#define DH_ 64
#define BS_ 8192
#define HD_ 1024

// ---------------- scratch (bf16 hi/lo splits) ----------------
__device__ __nv_bfloat16 g_qh[BS_*HD_], g_ql[BS_*HD_];
__device__ __nv_bfloat16 g_kh[BS_*HD_], g_kl[BS_*HD_];
__device__ __nv_bfloat16 g_vh[BS_*HD_], g_vl[BS_*HD_];
__device__ __nv_bfloat16 g_Wqh[D_*HD_], g_Wql[D_*HD_];
__device__ __nv_bfloat16 g_Wkh[D_*HD_], g_Wkl[D_*HD_];
__device__ __nv_bfloat16 g_Wvh[D_*HD_], g_Wvl[D_*HD_];
__device__ __nv_bfloat16 g_Woh[HD_*D_], g_Wol[HD_*D_];
__device__ __nv_bfloat16 g_Qh[BS_*HD_], g_Ql[BS_*HD_];   // [bh][s][dh]
__device__ __nv_bfloat16 g_Kh[BS_*HD_], g_Kl[BS_*HD_];   // [bh][s][dh]
__device__ __nv_bfloat16 g_Vph[BS_*HD_], g_Vpl[BS_*HD_]; // [bh][s][dh]
__device__ __nv_bfloat16 g_Vth[BS_*HD_], g_Vtl[BS_*HD_]; // [bh][dh][s]
__device__ __nv_bfloat16 g_AOh[BS_*HD_], g_AOl[BS_*HD_]; // [row][1024]

// ---------------- helpers ----------------
__device__ __forceinline__ void sp2(float a, float b, uint32_t& h, uint32_t& l) {
    __nv_bfloat16 ha = __float2bfloat16(a), hb = __float2bfloat16(b);
    float la = a - __bfloat162float(ha);
    float lb = b - __bfloat162float(hb);
    __nv_bfloat162 hp(ha, hb);
    __nv_bfloat162 lp(__float2bfloat16(la), __float2bfloat16(lb));
    h = *reinterpret_cast<uint32_t*>(&hp);
    l = *reinterpret_cast<uint32_t*>(&lp);
}

__device__ __forceinline__ void mma_bf16(float* d, uint32_t a0, uint32_t a1,
                                         uint32_t a2, uint32_t a3,
                                         uint32_t b0, uint32_t b1) {
    asm volatile(
        "mma.sync.aligned.m16n8k16.row.col.f32.bf16.bf16.f32 "
        "{%0,%1,%2,%3}, {%4,%5,%6,%7}, {%8,%9}, {%0,%1,%2,%3};"
        : "+f"(d[0]), "+f"(d[1]), "+f"(d[2]), "+f"(d[3])
        : "r"(a0), "r"(a1), "r"(a2), "r"(a3), "r"(b0), "r"(b1));
}

__device__ __forceinline__ void cp16(uint32_t s, const void* g) {
    asm volatile("cp.async.cg.shared.global [%0], [%1], 16;" :: "r"(s), "l"(g));
}
#define CP_COMMIT asm volatile("cp.async.commit_group;")
#define CP_WAIT0  asm volatile("cp.async.wait_group 0;" ::: "memory")
#define CP_WAIT1  asm volatile("cp.async.wait_group 1;" ::: "memory")

// ---------------------------------------------------------------------------
// split_in: fp32 -> bf16 hi/lo (flat)
// ---------------------------------------------------------------------------
__global__ void split_in(const float* __restrict__ x,
                         __nv_bfloat16* __restrict__ hi,
                         __nv_bfloat16* __restrict__ lo, int n4) {
    int i = blockIdx.x * blockDim.x + threadIdx.x;
    if (i < n4) {
        float4 v = ((const float4*)x)[i];
        uint2 hh, ll;
        sp2(v.x, v.y, hh.x, ll.x);
        sp2(v.z, v.w, hh.y, ll.y);
        ((uint2*)hi)[i] = hh;
        ((uint2*)lo)[i] = ll;
    }
}

// ---------------------------------------------------------------------------
// wsplit: W[K][N] fp32 -> Wt hi/lo [N][K] bf16 (transpose + split)
// block (32,8), tile 32x32
// ---------------------------------------------------------------------------
__global__ void wsplit(const float* __restrict__ W,
                       __nv_bfloat16* __restrict__ th,
                       __nv_bfloat16* __restrict__ tl) {
    __shared__ float t[32][33];
    const int k0 = blockIdx.y * 32, n0 = blockIdx.x * 32;
    const int tx = threadIdx.x, ty = threadIdx.y;
    #pragma unroll
    for (int r = 0; r < 4; r++)
        t[ty + r * 8][tx] = W[(size_t)(k0 + ty + r * 8) * 1024 + n0 + tx];
    __syncthreads();
    #pragma unroll
    for (int r = 0; r < 4; r++) {
        int n = ty + r * 8;
        float v = t[tx][n];
        __nv_bfloat16 hb = __float2bfloat16(v);
        float l = v - __bfloat162float(hb);
        th[(size_t)(n0 + n) * 1024 + k0 + tx] = hb;
        tl[(size_t)(n0 + n) * 1024 + k0 + tx] = __float2bfloat16(l);
    }
}

// ---------------------------------------------------------------------------
// Projection GEMM (bf16 3-term): C[M,1024] = A[M,1024] @ Wt^T + bias
//   A: hi/lo [M][1024] bf16 (k contiguous); B: hi/lo [N][K] bf16 (k contiguous)
// OUTMODE 0: head-packed split -> Ch/Cl at [((b*16+h)*2048+s)*64+d]
// OUTMODE 1: flat split        -> Ch/Cl at [row*1024+col]
// OUTMODE 2: fp32              -> Cf  at [row*1024+col]
// BM=BN=128, BK=32, 256 thr (2x4 warps), TM=TN=4.
// dyn smem: 2 bufs x {Ah,Al,Bh,Bl} x 128x40 bf16 = 81920 B
// ---------------------------------------------------------------------------
#define PK 40
#define PROJ_SMEM (2 * 4 * 128 * PK * 2)

template<int OUTMODE>
__global__ void __launch_bounds__(256, 2)
proj_bf16(const __nv_bfloat16* __restrict__ Ah, const __nv_bfloat16* __restrict__ Al,
          const __nv_bfloat16* __restrict__ Bh, const __nv_bfloat16* __restrict__ Bl,
          const float* __restrict__ bias,
          __nv_bfloat16* __restrict__ Ch, __nv_bfloat16* __restrict__ Cl,
          float* __restrict__ Cf) {
    extern __shared__ __nv_bfloat16 dsm[];
    // per-buffer offsets (bf16 units)
    const int BUF = 4 * 128 * PK;
    __nv_bfloat16* base = dsm;

    const int tid = threadIdx.x;
    const int m0 = blockIdx.y * 128, n0 = blockIdx.x * 128;
    const int w = tid >> 5, lane = tid & 31, g = lane >> 2, t = lane & 3;
    const int mw = (w & 1) * 64, nw = (w >> 1) * 32;

    const uint32_t smu = (uint32_t)__cvta_generic_to_shared(dsm);

    float acc[4][4][4] = {};

    auto stage = [&](int it, int buf) {
        const int k0 = it * 32;
        const uint32_t bu = smu + (uint32_t)buf * BUF * 2;
        // each array: 128 rows x 32 bf16 = 4 cp16/row, 512 chunks
        #pragma unroll
        for (int r = 0; r < 2; r++) {
            int c = tid + r * 256;
            int row = c >> 2, q8 = (c & 3) * 8;
            uint32_t o = (uint32_t)(row * PK + q8) * 2;
            size_t gi = (size_t)(m0 + row) * 1024 + k0 + q8;
            cp16(bu + o,                       Ah + gi);
            cp16(bu + 128 * PK * 2 + o,        Al + gi);
            size_t gb = (size_t)(n0 + row) * 1024 + k0 + q8;
            cp16(bu + 2 * 128 * PK * 2 + o,    Bh + gb);
            cp16(bu + 3 * 128 * PK * 2 + o,    Bl + gb);
        }
    };

    stage(0, 0); CP_COMMIT;

    for (int it = 0; it < 32; it++) {
        const int buf = it & 1;
        if (it + 1 < 32) { stage(it + 1, buf ^ 1); CP_COMMIT; CP_WAIT1; }
        else             { CP_WAIT0; }
        __syncthreads();

        const __nv_bfloat16* pAh = base + buf * BUF;
        const __nv_bfloat16* pAl = pAh + 128 * PK;
        const __nv_bfloat16* pBh = pAl + 128 * PK;
        const __nv_bfloat16* pBl = pBh + 128 * PK;

        #pragma unroll
        for (int ks = 0; ks < 32; ks += 16) {
            uint32_t bh[4][2], bl[4][2];
            #pragma unroll
            for (int j = 0; j < 4; j++) {
                const int n = nw + j * 8 + g;
                bh[j][0] = *(const uint32_t*)&pBh[n * PK + ks + 2 * t];
                bh[j][1] = *(const uint32_t*)&pBh[n * PK + ks + 2 * t + 8];
                bl[j][0] = *(const uint32_t*)&pBl[n * PK + ks + 2 * t];
                bl[j][1] = *(const uint32_t*)&pBl[n * PK + ks + 2 * t + 8];
            }
            #pragma unroll
            for (int i = 0; i < 4; i++) {
                const int m = mw + i * 16 + g;
                uint32_t ah0 = *(const uint32_t*)&pAh[m * PK + ks + 2 * t];
                uint32_t ah1 = *(const uint32_t*)&pAh[(m + 8) * PK + ks + 2 * t];
                uint32_t ah2 = *(const uint32_t*)&pAh[m * PK + ks + 2 * t + 8];
                uint32_t ah3 = *(const uint32_t*)&pAh[(m + 8) * PK + ks + 2 * t + 8];
                uint32_t al0 = *(const uint32_t*)&pAl[m * PK + ks + 2 * t];
                uint32_t al1 = *(const uint32_t*)&pAl[(m + 8) * PK + ks + 2 * t];
                uint32_t al2 = *(const uint32_t*)&pAl[m * PK + ks + 2 * t + 8];
                uint32_t al3 = *(const uint32_t*)&pAl[(m + 8) * PK + ks + 2 * t + 8];
                #pragma unroll
                for (int j = 0; j < 4; j++) {
                    mma_bf16(acc[i][j], ah0, ah1, ah2, ah3, bh[j][0], bh[j][1]);
                    mma_bf16(acc[i][j], al0, al1, al2, al3, bh[j][0], bh[j][1]);
                    mma_bf16(acc[i][j], ah0, ah1, ah2, ah3, bl[j][0], bl[j][1]);
                }
            }
        }
        __syncthreads();
    }

    // epilogue
    #pragma unroll
    for (int i = 0; i < 4; i++) {
        #pragma unroll
        for (int j = 0; j < 4; j++) {
            const int row0 = m0 + mw + i * 16 + g;
            const int col  = n0 + nw + j * 8 + t * 2;
            const float b0 = bias[col], b1 = bias[col + 1];
            float c00 = acc[i][j][0] + b0, c01 = acc[i][j][1] + b1;
            float c10 = acc[i][j][2] + b0, c11 = acc[i][j][3] + b1;
            if (OUTMODE == 2) {
                *(float2*)&Cf[(size_t)row0 * 1024 + col]       = make_float2(c00, c01);
                *(float2*)&Cf[(size_t)(row0 + 8) * 1024 + col] = make_float2(c10, c11);
            } else {
                size_t d0, d1;
                if (OUTMODE == 0) {
                    int bI = row0 >> 11, s = row0 & 2047, h = col >> 6, d = col & 63;
                    d0 = (((size_t)(bI * 16 + h) * 2048 + s) * 64 + d);
                    d1 = d0 + 8 * 64;
                } else {
                    d0 = (size_t)row0 * 1024 + col;
                    d1 = d0 + 8 * 1024;
                }
                uint32_t hu, lu;
                sp2(c00, c01, hu, lu);
                *(uint32_t*)&Ch[d0] = hu; *(uint32_t*)&Cl[d0] = lu;
                sp2(c10, c11, hu, lu);
                *(uint32_t*)&Ch[d1] = hu; *(uint32_t*)&Cl[d1] = lu;
            }
        }
    }
}

// ---------------------------------------------------------------------------
// vtrans: [bh][s][dh] -> [bh][dh][s] for hi and lo (pure bf16 permutation)
// grid (32 s-tiles, 64 bh), 256 threads, 64x64 tiles
// ---------------------------------------------------------------------------
__global__ void vtrans(const __nv_bfloat16* __restrict__ ih,
                       const __nv_bfloat16* __restrict__ il,
                       __nv_bfloat16* __restrict__ oh,
                       __nv_bfloat16* __restrict__ ol) {
    __shared__ __nv_bfloat16 t[64][72];
    const int s0 = blockIdx.x * 64;
    const int bh = blockIdx.y;
    const int tid = threadIdx.x;

    for (int pass = 0; pass < 2; pass++) {
        const __nv_bfloat16* src = pass ? il : ih;
        __nv_bfloat16* dst = pass ? ol : oh;
        #pragma unroll
        for (int r = 0; r < 8; r++) {
            int c = tid + r * 256;
            int row = c >> 5, c2 = (c & 31) * 2;
            *(uint32_t*)&t[row][c2] =
                *(const uint32_t*)&src[((size_t)bh * 2048 + s0 + row) * 64 + c2];
        }
        __syncthreads();
        #pragma unroll
        for (int r = 0; r < 8; r++) {
            int c = tid + r * 256;
            int d = c >> 5, s2 = (c & 31) * 2;
            __nv_bfloat162 p(t[s2][d], t[s2 + 1][d]);
            *(uint32_t*)&dst[((size_t)bh * 64 + d) * 2048 + s0 + s2] =
                *(uint32_t*)&p;
        }
        __syncthreads();
    }
}

// ---------------------------------------------------------------------------
// Fused attention, bf16 3-term.
// smem (bf16 units): sQh 0, sQl 9216, sKh0 18432, sKl0 27648, sKh1 36864,
//                    sKl1 46080, float region at 55296 (sM/sF/sL/sRed)
// Pass B overlays: sPh->sKh0, sPl->sKl0, sVh->sQh, sVl->sQl
// ---------------------------------------------------------------------------
#define PQ 72
#define PV 72
#define ATTN_SMEM (55296 * 2 + 896 * 4)

__global__ void __launch_bounds__(256, 1)
attn_bf16(float* __restrict__ alpha,
          __nv_bfloat16* __restrict__ AOh, __nv_bfloat16* __restrict__ AOl) {
    extern __shared__ __nv_bfloat16 dsm[];
    __nv_bfloat16* sQh = dsm;
    __nv_bfloat16* sQl = dsm + 9216;
    __nv_bfloat16* sKh0 = dsm + 18432;
    __nv_bfloat16* sKl0 = dsm + 27648;
    __nv_bfloat16* sKh1 = dsm + 36864;
    __nv_bfloat16* sKl1 = dsm + 46080;
    float* fsm  = (float*)(dsm + 55296);
    float* sM   = fsm;
    float* sF   = fsm + 128;
    float* sL   = fsm + 256;
    float* sRed = fsm + 384;

    const int tid = threadIdx.x;
    const int w = tid >> 5, lane = tid & 31, g = lane >> 2, t = lane & 3;
    const int mw = (w & 1) * 64;
    const int wc = w >> 1;
    const int q0 = blockIdx.x * 128;
    const int bh = blockIdx.y;

    const __nv_bfloat16* Qhb = g_Qh + ((size_t)bh * 2048 + q0) * 64;
    const __nv_bfloat16* Qlb = g_Ql + ((size_t)bh * 2048 + q0) * 64;
    const __nv_bfloat16* Khb = g_Kh + (size_t)bh * 2048 * 64;
    const __nv_bfloat16* Klb = g_Kl + (size_t)bh * 2048 * 64;
    const __nv_bfloat16* Vthb = g_Vth + (size_t)bh * 64 * 2048;
    const __nv_bfloat16* Vtlb = g_Vtl + (size_t)bh * 64 * 2048;
    float* Ab = alpha + ((size_t)bh * 2048 + q0) * 2048;

    const uint32_t smu = (uint32_t)__cvta_generic_to_shared(dsm);

    if (tid < 128) { sM[tid] = -3e38f; sL[tid] = 0.f; }

    // stage Q (once): 128 rows x 64 bf16 = 8 cp16/row per component
    #pragma unroll
    for (int r = 0; r < 4; r++) {
        int c = tid + r * 256;
        int row = c >> 3, q8 = (c & 7) * 8;
        uint32_t o = (uint32_t)(row * PQ + q8) * 2;
        size_t gi = (size_t)row * 64 + q8;
        cp16(smu + o,            Qhb + gi);
        cp16(smu + 9216 * 2 + o, Qlb + gi);
    }
    auto stageK = [&](int kt, int buf) {
        const uint32_t bh_off = (buf ? 36864u : 18432u) * 2;
        const uint32_t bl_off = (buf ? 46080u : 27648u) * 2;
        const size_t src = (size_t)kt * 128 * 64;
        #pragma unroll
        for (int r = 0; r < 4; r++) {
            int c = tid + r * 256;
            int row = c >> 3, q8 = (c & 7) * 8;
            uint32_t o = (uint32_t)(row * PQ + q8) * 2;
            cp16(smu + bh_off + o, Khb + src + (size_t)row * 64 + q8);
            cp16(smu + bl_off + o, Klb + src + (size_t)row * 64 + q8);
        }
    };
    stageK(0, 0);
    CP_COMMIT;

    // =================== PASS A ===================
    for (int kt = 0; kt < 16; kt++) {
        const __nv_bfloat16* pKh = (kt & 1) ? sKh1 : sKh0;
        const __nv_bfloat16* pKl = (kt & 1) ? sKl1 : sKl0;
        if (kt + 1 < 16) { stageK(kt + 1, (kt & 1) ^ 1); CP_COMMIT; CP_WAIT1; }
        else             { CP_WAIT0; }
        __syncthreads();

        float acc[4][4][4] = {};
        #pragma unroll
        for (int ks = 0; ks < 64; ks += 16) {
            uint32_t kh[4][2], kl[4][2];
            #pragma unroll
            for (int j = 0; j < 4; j++) {
                const int n = wc * 32 + j * 8 + g;
                kh[j][0] = *(const uint32_t*)&pKh[n * PQ + ks + 2 * t];
                kh[j][1] = *(const uint32_t*)&pKh[n * PQ + ks + 2 * t + 8];
                kl[j][0] = *(const uint32_t*)&pKl[n * PQ + ks + 2 * t];
                kl[j][1] = *(const uint32_t*)&pKl[n * PQ + ks + 2 * t + 8];
            }
            #pragma unroll
            for (int i = 0; i < 4; i++) {
                const int m = mw + i * 16 + g;
                uint32_t qh0 = *(const uint32_t*)&sQh[m * PQ + ks + 2 * t];
                uint32_t qh1 = *(const uint32_t*)&sQh[(m + 8) * PQ + ks + 2 * t];
                uint32_t qh2 = *(const uint32_t*)&sQh[m * PQ + ks + 2 * t + 8];
                uint32_t qh3 = *(const uint32_t*)&sQh[(m + 8) * PQ + ks + 2 * t + 8];
                uint32_t ql0 = *(const uint32_t*)&sQl[m * PQ + ks + 2 * t];
                uint32_t ql1 = *(const uint32_t*)&sQl[(m + 8) * PQ + ks + 2 * t];
                uint32_t ql2 = *(const uint32_t*)&sQl[m * PQ + ks + 2 * t + 8];
                uint32_t ql3 = *(const uint32_t*)&sQl[(m + 8) * PQ + ks + 2 * t + 8];
                #pragma unroll
                for (int j = 0; j < 4; j++) {
                    mma_bf16(acc[i][j], qh0, qh1, qh2, qh3, kh[j][0], kh[j][1]);
                    mma_bf16(acc[i][j], ql0, ql1, ql2, ql3, kh[j][0], kh[j][1]);
                    mma_bf16(acc[i][j], qh0, qh1, qh2, qh3, kl[j][0], kl[j][1]);
                }
            }
        }
        // scale + write raw S
        #pragma unroll
        for (int i = 0; i < 4; i++)
            #pragma unroll
            for (int j = 0; j < 4; j++)
                #pragma unroll
                for (int r = 0; r < 4; r++) acc[i][j][r] *= 0.125f;

        #pragma unroll
        for (int i = 0; i < 4; i++) {
            const int row = mw + i * 16 + g;
            #pragma unroll
            for (int j = 0; j < 4; j++) {
                const int cc = kt * 128 + wc * 32 + j * 8 + t * 2;
                *(float2*)&Ab[(size_t)row * 2048 + cc]       = make_float2(acc[i][j][0], acc[i][j][1]);
                *(float2*)&Ab[(size_t)(row + 8) * 2048 + cc] = make_float2(acc[i][j][2], acc[i][j][3]);
            }
        }

        // ---- row max ----
        float rmax[8];
        #pragma unroll
        for (int i = 0; i < 4; i++) {
            float m0v = -3e38f, m1v = -3e38f;
            #pragma unroll
            for (int j = 0; j < 4; j++) {
                m0v = fmaxf(m0v, fmaxf(acc[i][j][0], acc[i][j][1]));
                m1v = fmaxf(m1v, fmaxf(acc[i][j][2], acc[i][j][3]));
            }
            rmax[i * 2] = m0v; rmax[i * 2 + 1] = m1v;
        }
        #pragma unroll
        for (int o = 1; o <= 2; o <<= 1)
            #pragma unroll
            for (int e = 0; e < 8; e++)
                rmax[e] = fmaxf(rmax[e], __shfl_xor_sync(0xffffffffu, rmax[e], o));
        if (t == 0) {
            #pragma unroll
            for (int i = 0; i < 4; i++) {
                sRed[wc * 128 + mw + i * 16 + g]     = rmax[i * 2];
                sRed[wc * 128 + mw + i * 16 + g + 8] = rmax[i * 2 + 1];
            }
        }
        __syncthreads();
        if (tid < 128) {
            float tm = fmaxf(fmaxf(sRed[tid], sRed[128 + tid]),
                             fmaxf(sRed[256 + tid], sRed[384 + tid]));
            float mo = sM[tid];
            float mn = fmaxf(mo, tm);
            sM[tid] = mn;
            sF[tid] = __expf(mo - mn);
        }
        __syncthreads();

        // ---- row sum of exp ----
        float rsum[8];
        #pragma unroll
        for (int i = 0; i < 4; i++) {
            const int row = mw + i * 16 + g;
            const float mn0 = sM[row], mn1 = sM[row + 8];
            float s0 = 0.f, s1 = 0.f;
            #pragma unroll
            for (int j = 0; j < 4; j++) {
                s0 += __expf(acc[i][j][0] - mn0) + __expf(acc[i][j][1] - mn0);
                s1 += __expf(acc[i][j][2] - mn1) + __expf(acc[i][j][3] - mn1);
            }
            rsum[i * 2] = s0; rsum[i * 2 + 1] = s1;
        }
        #pragma unroll
        for (int o = 1; o <= 2; o <<= 1)
            #pragma unroll
            for (int e = 0; e < 8; e++)
                rsum[e] += __shfl_xor_sync(0xffffffffu, rsum[e], o);
        if (t == 0) {
            #pragma unroll
            for (int i = 0; i < 4; i++) {
                sRed[wc * 128 + mw + i * 16 + g]     = rsum[i * 2];
                sRed[wc * 128 + mw + i * 16 + g + 8] = rsum[i * 2 + 1];
            }
        }
        __syncthreads();
        if (tid < 128) {
            sL[tid] = sL[tid] * sF[tid] +
                      (sRed[tid] + sRed[128 + tid] + sRed[256 + tid] + sRed[384 + tid]);
        }
        __syncthreads();
    }

    if (tid < 128) sL[tid] = 1.0f / sL[tid];
    __syncthreads();

    // =================== PASS B ===================
    __nv_bfloat16* sPh = sKh0;
    __nv_bfloat16* sPl = sKl0;
    __nv_bfloat16* sVh = sQh;   // 64 x PV
    __nv_bfloat16* sVl = sQl;

    float accO[4][2][4] = {};
    const int pr = tid & 127;
    const int pc = (tid >> 7) * 32;
    const float rm = sM[pr];
    const float rl = sL[pr];

    for (int ch = 0; ch < 32; ch++) {
        const int kb = ch * 64;
        // stage Vt chunk: 64 d-rows x 64 s
        #pragma unroll
        for (int r = 0; r < 2; r++) {
            int c = tid + r * 256;
            int d = c >> 3, q8 = (c & 7) * 8;
            uint32_t o = (uint32_t)(d * PV + q8) * 2;
            size_t gi = (size_t)d * 2048 + kb + q8;
            cp16(smu + o,            Vthb + gi);
            cp16(smu + 9216 * 2 + o, Vtlb + gi);
        }
        CP_COMMIT;

        // P: read raw S, normalize, write alpha fp32 + smem bf16 split
        {
            float* rowp = Ab + (size_t)pr * 2048 + kb + pc;
            #pragma unroll
            for (int u = 0; u < 8; u++) {
                float4 s4 = *(const float4*)(rowp + u * 4);
                float4 p4;
                p4.x = __expf(s4.x - rm) * rl;
                p4.y = __expf(s4.y - rm) * rl;
                p4.z = __expf(s4.z - rm) * rl;
                p4.w = __expf(s4.w - rm) * rl;
                *(float4*)(rowp + u * 4) = p4;
                uint32_t hu, lu;
                sp2(p4.x, p4.y, hu, lu);
                *(uint32_t*)&sPh[pr * PQ + pc + u * 4]     = hu;
                *(uint32_t*)&sPl[pr * PQ + pc + u * 4]     = lu;
                sp2(p4.z, p4.w, hu, lu);
                *(uint32_t*)&sPh[pr * PQ + pc + u * 4 + 2] = hu;
                *(uint32_t*)&sPl[pr * PQ + pc + u * 4 + 2] = lu;
            }
        }
        CP_WAIT0;
        __syncthreads();

        // O += P * V
        #pragma unroll
        for (int ks = 0; ks < 64; ks += 16) {
            uint32_t vh[2][2], vl[2][2];
            #pragma unroll
            for (int j = 0; j < 2; j++) {
                const int n = wc * 16 + j * 8 + g;
                vh[j][0] = *(const uint32_t*)&sVh[n * PV + ks + 2 * t];
                vh[j][1] = *(const uint32_t*)&sVh[n * PV + ks + 2 * t + 8];
                vl[j][0] = *(const uint32_t*)&sVl[n * PV + ks + 2 * t];
                vl[j][1] = *(const uint32_t*)&sVl[n * PV + ks + 2 * t + 8];
            }
            #pragma unroll
            for (int i = 0; i < 4; i++) {
                const int m = mw + i * 16 + g;
                uint32_t ph0 = *(const uint32_t*)&sPh[m * PQ + ks + 2 * t];
                uint32_t ph1 = *(const uint32_t*)&sPh[(m + 8) * PQ + ks + 2 * t];
                uint32_t ph2 = *(const uint32_t*)&sPh[m * PQ + ks + 2 * t + 8];
                uint32_t ph3 = *(const uint32_t*)&sPh[(m + 8) * PQ + ks + 2 * t + 8];
                uint32_t pl0 = *(const uint32_t*)&sPl[m * PQ + ks + 2 * t];
                uint32_t pl1 = *(const uint32_t*)&sPl[(m + 8) * PQ + ks + 2 * t];
                uint32_t pl2 = *(const uint32_t*)&sPl[m * PQ + ks + 2 * t + 8];
                uint32_t pl3 = *(const uint32_t*)&sPl[(m + 8) * PQ + ks + 2 * t + 8];
                #pragma unroll
                for (int j = 0; j < 2; j++) {
                    mma_bf16(accO[i][j], ph0, ph1, ph2, ph3, vh[j][0], vh[j][1]);
                    mma_bf16(accO[i][j], pl0, pl1, pl2, pl3, vh[j][0], vh[j][1]);
                    mma_bf16(accO[i][j], ph0, ph1, ph2, ph3, vl[j][0], vl[j][1]);
                }
            }
        }
        __syncthreads();
    }

    // epilogue: AO split (flat [row][1024], col = h*64 + d)
    const int b = bh >> 4, h = bh & 15;
    #pragma unroll
    for (int i = 0; i < 4; i++) {
        #pragma unroll
        for (int j = 0; j < 2; j++) {
            const int row = q0 + mw + i * 16 + g;
            const int col = h * 64 + wc * 16 + j * 8 + t * 2;
            uint32_t hu, lu;
            size_t d0 = ((size_t)(b * 2048 + row)) * 1024 + col;
            sp2(accO[i][j][0], accO[i][j][1], hu, lu);
            *(uint32_t*)&AOh[d0] = hu; *(uint32_t*)&AOl[d0] = lu;
            size_t d1 = ((size_t)(b * 2048 + row + 8)) * 1024 + col;
            sp2(accO[i][j][2], accO[i][j][3], hu, lu);
            *(uint32_t*)&AOh[d1] = hu; *(uint32_t*)&AOl[d1] = lu;
        }
    }
}

// ---------------------------------------------------------------------------
extern "C" void kernel_launch(void* const* d_in, const int* in_sizes, int n_in,
                              void* d_out, int out_size) {
    const float* q  = (const float*)d_in[0];
    const float* k  = (const float*)d_in[1];
    const float* v  = (const float*)d_in[2];
    const float* Wq = (const float*)d_in[3];
    const float* bq = (const float*)d_in[4];
    const float* Wk = (const float*)d_in[5];
    const float* bk = (const float*)d_in[6];
    const float* Wv = (const float*)d_in[7];
    const float* bv = (const float*)d_in[8];
    const float* Wo = (const float*)d_in[9];
    const float* bo = (const float*)d_in[10];

    float* out   = (float*)d_out;
    float* alpha = out + (size_t)B_ * S_ * D_;

    // resolve scratch symbols
    __nv_bfloat16 *qh,*ql,*kh,*kl,*vh,*vl;
    __nv_bfloat16 *Wqh,*Wql,*Wkh,*Wkl,*Wvh,*Wvl,*Woh,*Wol;
    __nv_bfloat16 *Qh,*Ql,*Kh,*Kl,*Vph,*Vpl,*Vth,*Vtl,*AOh,*AOl;
    cudaGetSymbolAddress((void**)&qh, g_qh);   cudaGetSymbolAddress((void**)&ql, g_ql);
    cudaGetSymbolAddress((void**)&kh, g_kh);   cudaGetSymbolAddress((void**)&kl, g_kl);
    cudaGetSymbolAddress((void**)&vh, g_vh);   cudaGetSymbolAddress((void**)&vl, g_vl);
    cudaGetSymbolAddress((void**)&Wqh, g_Wqh); cudaGetSymbolAddress((void**)&Wql, g_Wql);
    cudaGetSymbolAddress((void**)&Wkh, g_Wkh); cudaGetSymbolAddress((void**)&Wkl, g_Wkl);
    cudaGetSymbolAddress((void**)&Wvh, g_Wvh); cudaGetSymbolAddress((void**)&Wvl, g_Wvl);
    cudaGetSymbolAddress((void**)&Woh, g_Woh); cudaGetSymbolAddress((void**)&Wol, g_Wol);
    cudaGetSymbolAddress((void**)&Qh, g_Qh);   cudaGetSymbolAddress((void**)&Ql, g_Ql);
    cudaGetSymbolAddress((void**)&Kh, g_Kh);   cudaGetSymbolAddress((void**)&Kl, g_Kl);
    cudaGetSymbolAddress((void**)&Vph, g_Vph); cudaGetSymbolAddress((void**)&Vpl, g_Vpl);
    cudaGetSymbolAddress((void**)&Vth, g_Vth); cudaGetSymbolAddress((void**)&Vtl, g_Vtl);
    cudaGetSymbolAddress((void**)&AOh, g_AOh); cudaGetSymbolAddress((void**)&AOl, g_AOl);

    static bool attr_set = false;
    if (!attr_set) {
        cudaFuncSetAttribute(proj_bf16<0>, cudaFuncAttributeMaxDynamicSharedMemorySize, PROJ_SMEM);
        cudaFuncSetAttribute(proj_bf16<1>, cudaFuncAttributeMaxDynamicSharedMemorySize, PROJ_SMEM);
        cudaFuncSetAttribute(proj_bf16<2>, cudaFuncAttributeMaxDynamicSharedMemorySize, PROJ_SMEM);
        cudaFuncSetAttribute(attn_bf16, cudaFuncAttributeMaxDynamicSharedMemorySize, ATTN_SMEM);
        attr_set = true;
    }

    const int n4 = BS_ * HD_ / 4;
    split_in<<<(n4 + 255) / 256, 256>>>(q, qh, ql, n4);
    split_in<<<(n4 + 255) / 256, 256>>>(k, kh, kl, n4);
    split_in<<<(n4 + 255) / 256, 256>>>(v, vh, vl, n4);

    dim3 gW(32, 32), bW(32, 8);
    wsplit<<<gW, bW>>>(Wq, Wqh, Wql);
    wsplit<<<gW, bW>>>(Wk, Wkh, Wkl);
    wsplit<<<gW, bW>>>(Wv, Wvh, Wvl);
    wsplit<<<gW, bW>>>(Wo, Woh, Wol);

    dim3 gProj(HD_ / 128, BS_ / 128);   // (8, 64)
    proj_bf16<0><<<gProj, 256, PROJ_SMEM>>>(qh, ql, Wqh, Wql, bq, Qh, Ql, nullptr);
    proj_bf16<0><<<gProj, 256, PROJ_SMEM>>>(kh, kl, Wkh, Wkl, bk, Kh, Kl, nullptr);
    proj_bf16<0><<<gProj, 256, PROJ_SMEM>>>(vh, vl, Wvh, Wvl, bv, Vph, Vpl, nullptr);

    vtrans<<<dim3(32, 64), 256>>>(Vph, Vpl, Vth, Vtl);

    dim3 gAttn(S_ / 128, B_ * H_);      // (16, 64)
    attn_bf16<<<gAttn, 256, ATTN_SMEM>>>(alpha, AOh, AOl);

    proj_bf16<2><<<gProj, 256, PROJ_SMEM>>>(AOh, AOl, Woh, Wol, bo, nullptr, nullptr, out);
}